// round 2
// baseline (speedup 1.0000x reference)
#include <cuda_runtime.h>
#include <math.h>

typedef unsigned long long ULL;

#define FMA2(d, a, b) \
    asm("fma.rn.f32x2 %0, %1, %2, %3;" : "=l"(d) : "l"(a), "l"(b), "l"(d))

// S[H=65, C=224] = sum_b h~(r_zab) (outer) G(n_zab, f_zb);  out = W2~ * S
// G memory columns are PERMUTED so lane tx owns {4tx..4tx+3, 128+2tx, 129+2tx, 192+tx}:
//   logical L<128:      mem = 4*(L%32) + L/32
//   logical 128<=L<192: mem = 128 + 2*((L-128)%32) + (L-128)/32
//   logical L>=192:     mem = L
__device__ float g_scratch[2 * 2 * 160 * 64];   // [p][z*160+a][64]

__global__ void __launch_bounds__(256, 2)
conv_kernel(const float* __restrict__ feat,
            const float* __restrict__ geo,
            const float* __restrict__ W1,
            const float* __restrict__ b1,
            const float* __restrict__ W2,
            const float* __restrict__ b2p)
{
    constexpr int A = 160, B_HALF = 80, DIM = 64;
    constexpr float C0   = 0.28209479177387814f;
    constexpr float NC00 = 0.6266570686577501f;
    constexpr float NC01 = 1.0854018854473597f;
    constexpr float NC10 = 0.4431134627263790f;
    constexpr float NC11 = 0.7674950356098778f;
    constexpr float NCZ0 = 0.8862269254527580f;
    constexpr float NCZ1 = 1.5349900712197556f;
    constexpr float E1   = 0.19947114020071635f;
    constexpr float AL   = 0.34549414947133547f;
    constexpr float C0S3 = 0.16286750396763996f;
    constexpr float QZ   = 0.05758236f;

    extern __shared__ float sm[];
    // buffers: buf k at offset k*4736: G[16][224] then h[16][72]
    float* S_sh = sm;                // [65][228] phase-2 (reuses buffers)
    float* w1s  = sm + 14848;
    float* b1s  = sm + 14912;

    const int a = blockIdx.x, z = blockIdx.y, p = blockIdx.z;
    const int tid = threadIdx.x;
    if (tid < 64) { w1s[tid] = W1[tid]; b1s[tid] = b1[tid]; }
    __syncthreads();

    const int ty = tid >> 5, tx = tid & 31;
    ULL   S2[9][3];
    float S1[9];
    #pragma unroll
    for (int m = 0; m < 9; m++) {
        S2[m][0] = 0ull; S2[m][1] = 0ull; S2[m][2] = 0ull; S1[m] = 0.0f;
    }

    const int bl = tid >> 4, vv = tid & 15;
    const float* geoA = geo + (size_t)((z * A + a) * A) * 3;
    const float* fz   = feat + (size_t)z * A * DIM;
    const int bbase = p * B_HALF + bl;

    // prefetch chunk 0
    float gx, gy, gz, f0v, p0, p1, p2;
    {
        const int b = bbase;
        gx = __ldg(geoA + b * 3 + 0);
        gy = __ldg(geoA + b * 3 + 1);
        gz = __ldg(geoA + b * 3 + 2);
        const float* f = fz + b * DIM;
        f0v = __ldg(f + vv);
        p0 = __ldg(f + 16 + 3 * vv);
        p1 = __ldg(f + 17 + 3 * vv);
        p2 = __ldg(f + 18 + 3 * vv);
    }

    for (int c = 0; c < 5; c++) {
        float* gbuf = sm + (c & 1) * 4736;
        float* hbuf = gbuf + 3584;

        // ---- build G,h from prefetched regs ----
        {
            const float r  = sqrtf(gx * gx + gy * gy + gz * gz);
            const bool is0 = (r == 0.0f);
            const float inv = is0 ? 1.0f : (1.0f / r);
            const float v0 = gy * inv, v1 = gz * inv, v2 = gx * inv;

            float* hrow = hbuf + bl * 72;
            #pragma unroll
            for (int m = 0; m < 4; m++) {
                const int hh = vv + 16 * m;
                hrow[hh] = fmaxf(fmaf(r, w1s[hh], b1s[hh]), 0.0f);
            }
            if (vv == 0) hrow[64] = 1.0f;
            else if (vv <= 7) hrow[64 + vv] = 0.0f;

            const float ncA = is0 ? NCZ0 : NC00;
            const float ncB = is0 ? NCZ1 : NC01;
            const float ncC = is0 ? NCZ0 : NC10;
            const float ncD = is0 ? NCZ1 : NC11;
            const float s = v0 * p0 + v1 * p1 + v2 * p2;

            float* G = gbuf + bl * 224;
            G[4 * vv]      = ncA * C0 * f0v;              // L=v
            G[64 + 4 * vv] = ncB * C0 * s;                // L=16+v
            const float t2 = ncC * C0 * f0v;
            G[4 * vv + 1]  = t2 * v0;                     // L=32+v
            G[65 + 4 * vv] = t2 * v1;                     // L=48+v
            G[4 * vv + 2]  = t2 * v2;                     // L=64+v
            const float t3a = ncD * C0S3;
            G[66 + 4 * vv] = t3a * p0;                    // L=80+v
            G[4 * vv + 3]  = t3a * p1;                    // L=96+v
            G[67 + 4 * vv] = t3a * p2;                    // L=112+v
            const float t3b = ncD * E1;
            G[128 + 2 * vv] = t3b * (p1 * v2 - p2 * v1);  // L=128+v
            G[160 + 2 * vv] = t3b * (p2 * v0 - p0 * v2);  // L=144+v
            G[129 + 2 * vv] = t3b * (p0 * v1 - p1 * v0);  // L=160+v
            if (!is0) {
                const float t3c = ncD * AL;
                G[161 + 2 * vv] = t3c * (v0 * s - p0 * (1.0f / 3.0f)); // L=176+v
                G[192 + vv]     = t3c * (v1 * s - p1 * (1.0f / 3.0f)); // L=192+v
                G[208 + vv]     = t3c * (v2 * s - p2 * (1.0f / 3.0f)); // L=208+v
            } else {
                const float q = ncD * QZ;
                G[161 + 2 * vv] = q * p0;
                G[192 + vv]     = -2.0f * q * p1;
                G[208 + vv]     = q * p2;
            }
        }

        // ---- prefetch next chunk (overlaps sync + FMA loop) ----
        if (c < 4) {
            const int b = bbase + (c + 1) * 16;
            gx = __ldg(geoA + b * 3 + 0);
            gy = __ldg(geoA + b * 3 + 1);
            gz = __ldg(geoA + b * 3 + 2);
            const float* f = fz + b * DIM;
            f0v = __ldg(f + vv);
            p0 = __ldg(f + 16 + 3 * vv);
            p1 = __ldg(f + 17 + 3 * vv);
            p2 = __ldg(f + 18 + 3 * vv);
        }
        __syncthreads();   // single sync per chunk (double buffered)

        // ---- rank-16 packed outer-product update ----
        #pragma unroll 4
        for (int j = 0; j < 16; j++) {
            const float* grow = gbuf + j * 224;
            const float* hrow = hbuf + j * 72;
            const ulonglong2 gg = *(const ulonglong2*)(grow + 4 * tx);
            const ULL g01 = gg.x, g23 = gg.y;
            const ULL g45 = *(const ULL*)(grow + 128 + 2 * tx);
            const float gc = grow[192 + tx];
            #pragma unroll
            for (int m = 0; m < 9; m++) {
                const float hs = hrow[ty + 8 * m];
                ULL h2;
                asm("mov.b64 %0, {%1, %1};" : "=l"(h2) : "f"(hs));
                FMA2(S2[m][0], h2, g01);
                FMA2(S2[m][1], h2, g23);
                FMA2(S2[m][2], h2, g45);
                S1[m] = fmaf(hs, gc, S1[m]);
            }
        }
        __syncthreads();
    }

    // ---- spill S (mem-column layout, stride 228) ----
    #pragma unroll
    for (int m = 0; m < 9; m++) {
        const int hh = ty + 8 * m;
        if (hh <= 64) {
            float* rp = S_sh + hh * 228;
            const float2 s01 = *(const float2*)&S2[m][0];
            const float2 s23 = *(const float2*)&S2[m][1];
            const float2 s45 = *(const float2*)&S2[m][2];
            *(float4*)(rp + 4 * tx) = make_float4(s01.x, s01.y, s23.x, s23.y);
            *(float2*)(rp + 128 + 2 * tx) = s45;
            rp[192 + tx] = S1[m];
        }
    }
    __syncthreads();

    // ---- phase 2: contract with W2 (+b2 via H row 64) ----
    const int oi = tid >> 2, part = tid & 3;
    float acc = 0.0f;
    const int hcnt = (part == 0) ? 17 : 16;
    if (oi < 16) {                                   // l=0 outputs
        const int u = oi;
        for (int t = 0; t < hcnt; t++) {
            const int hh = (t == 16) ? 64 : part * 16 + t;
            const float4* w4 = (const float4*)((hh == 64) ? b2p : (W2 + hh * 1536));
            const float* Sr = S_sh + hh * 228;
            #pragma unroll
            for (int v4 = 0; v4 < 4; v4++) {
                const float4 wa = w4[u * 4 + v4];        // w[u*16+v]
                const float4 wb = w4[64 + u * 4 + v4];   // w[256+u*16+v]
                const int mb = 16 * v4;                  // mem col 4v, v=4*v4+c
                acc = fmaf(wa.x, Sr[mb + 0],  acc);
                acc = fmaf(wa.y, Sr[mb + 4],  acc);
                acc = fmaf(wa.z, Sr[mb + 8],  acc);
                acc = fmaf(wa.w, Sr[mb + 12], acc);
                acc = fmaf(wb.x, Sr[64 + mb + 0],  acc);
                acc = fmaf(wb.y, Sr[64 + mb + 4],  acc);
                acc = fmaf(wb.z, Sr[64 + mb + 8],  acc);
                acc = fmaf(wb.w, Sr[64 + mb + 12], acc);
            }
        }
    } else {                                         // l=1 outputs (u, i)
        const int qq = oi - 16;
        const int u  = qq / 3;
        const int i  = qq - 3 * u;
        const int B2  = (i == 0) ? 1   : (i == 1) ? 65  : 2;    // lf=1 (l_in=0)
        const int B3A = (i == 0) ? 66  : (i == 1) ? 3   : 67;   // lf=0
        const int B3B = (i == 0) ? 128 : (i == 1) ? 160 : 129;  // lf=1
        const int B3C = (i == 0) ? 161 : (i == 1) ? 192 : 208;  // lf=2
        const int S3C = (i == 0) ? 2 : 1;
        for (int t = 0; t < hcnt; t++) {
            const int hh = (t == 16) ? 64 : part * 16 + t;
            const float4* w4 = (const float4*)((hh == 64) ? b2p : (W2 + hh * 1536));
            const float* Sr = S_sh + hh * 228;
            #pragma unroll
            for (int v4 = 0; v4 < 4; v4++) {
                const float4 wc = w4[128 + u * 4 + v4];          // w[512+u*16+v]
                const float4 w0 = w4[192 + 12 * u + 3 * v4];     // w[768+(u*16+v)*3+k]
                const float4 w1v = w4[193 + 12 * u + 3 * v4];
                const float4 w2v = w4[194 + 12 * u + 3 * v4];
                const int v = 4 * v4;
                #define L1V(vn, K0, K1, K2, WC)                       \
                    acc = fmaf(WC, Sr[B2  + 4 * (vn)], acc);          \
                    acc = fmaf(K0, Sr[B3A + 4 * (vn)], acc);          \
                    acc = fmaf(K1, Sr[B3B + 2 * (vn)], acc);          \
                    acc = fmaf(K2, Sr[B3C + S3C * (vn)], acc);
                L1V(v + 0, w0.x, w0.y, w0.z, wc.x)
                L1V(v + 1, w0.w, w1v.x, w1v.y, wc.y)
                L1V(v + 2, w1v.z, w1v.w, w2v.x, wc.z)
                L1V(v + 3, w2v.y, w2v.z, w2v.w, wc.w)
                #undef L1V
            }
        }
    }
    acc += __shfl_down_sync(0xffffffffu, acc, 1);
    acc += __shfl_down_sync(0xffffffffu, acc, 2);
    if (part == 0)
        g_scratch[((p * 2 + z) * A + a) * DIM + oi] = acc;
}

__global__ void reduce_kernel(const float* __restrict__ maskp,
                              float* __restrict__ out)
{
    const int i = blockIdx.x * 256 + threadIdx.x;
    if (i < 2 * 160 * 64) {
        const float s = g_scratch[i] + g_scratch[2 * 160 * 64 + i];
        out[i] = s * __ldg(maskp + (i >> 6));
    }
}

extern "C" void kernel_launch(void* const* d_in, const int* in_sizes, int n_in,
                              void* d_out, int out_size)
{
    const float* feat  = (const float*)d_in[0];
    const float* geo   = (const float*)d_in[1];
    const float* maskp = (const float*)d_in[2];
    const float* W1    = (const float*)d_in[3];
    const float* b1    = (const float*)d_in[4];
    const float* W2    = (const float*)d_in[5];
    const float* b2    = (const float*)d_in[6];
    float* out = (float*)d_out;

    const int smem_bytes = 14976 * 4;  // 59,904 B
    static int configured = 0;
    cudaFuncSetAttribute(conv_kernel, cudaFuncAttributeMaxDynamicSharedMemorySize,
                         smem_bytes);
    (void)configured;

    dim3 grid(160, 2, 2);
    conv_kernel<<<grid, 256, smem_bytes>>>(feat, geo, W1, b1, W2, b2);
    reduce_kernel<<<(2 * 160 * 64 + 255) / 256, 256>>>(maskp, out);
}